// round 16
// baseline (speedup 1.0000x reference)
#include <cuda_runtime.h>
#include <cuda_fp16.h>
#include <cstdint>

#define B_SZ 2
#define T_SZ 2048
#define C_SZ 2048
#define NH 16
#define NKV 4
#define HD 128
#define RMS_EPS 1.1920929e-07f
#define ATT_SCALE 0.08838834764831845f   // 1/sqrt(128)
#define SM_SHIFT 3.0f                    // static softmax shift (|s|<=11.32)

// ---------------- scratch (static device globals; no allocation) ----------------
__device__ __half g_q[(size_t)B_SZ * T_SZ * NH * HD];           // q (rope+rms) half
__device__ __half g_k[(size_t)B_SZ * T_SZ * NKV * HD];          // k (rope+rms) half
__device__ __half g_vt[(size_t)B_SZ * NKV * HD * T_SZ];         // v transposed half
__device__ float  g_y[(size_t)B_SZ * T_SZ * C_SZ];              // attn out fp32

// ---------------- helpers ----------------------------------------------------------
__device__ __forceinline__ uint32_t packh2(float lo, float hi) {
    __half2 h = __floats2half2_rn(lo, hi);
    return *(uint32_t*)&h;
}

__device__ __forceinline__ void mma_f16(float* c, const uint32_t* a, const uint32_t* b) {
    asm volatile("mma.sync.aligned.m16n8k16.row.col.f32.f16.f16.f32 "
                 "{%0,%1,%2,%3}, {%4,%5,%6,%7}, {%8,%9}, {%0,%1,%2,%3};"
                 : "+f"(c[0]), "+f"(c[1]), "+f"(c[2]), "+f"(c[3])
                 : "r"(a[0]), "r"(a[1]), "r"(a[2]), "r"(a[3]),
                   "r"(b[0]), "r"(b[1]));
}

__device__ __forceinline__ void ldsm_x4(uint32_t* r, uint32_t saddr) {
    asm volatile("ldmatrix.sync.aligned.m8n8.x4.shared.b16 {%0,%1,%2,%3}, [%4];"
                 : "=r"(r[0]), "=r"(r[1]), "=r"(r[2]), "=r"(r[3]) : "r"(saddr));
}
__device__ __forceinline__ void ldsm_x2(uint32_t* r, uint32_t saddr) {
    asm volatile("ldmatrix.sync.aligned.m8n8.x2.shared.b16 {%0,%1}, [%2];"
                 : "=r"(r[0]), "=r"(r[1]) : "r"(saddr));
}

#define CP_ASYNC16(dst_u32, src_ptr) \
    asm volatile("cp.async.cg.shared.global [%0], [%1], 16;" :: "r"(dst_u32), "l"(src_ptr))
#define CP_COMMIT() asm volatile("cp.async.commit_group;" ::: "memory")
#define CP_WAIT(n)  asm volatile("cp.async.wait_group %0;" :: "n"(n) : "memory")

__device__ __forceinline__ uint32_t smem_u32(const void* p) {
    return (uint32_t)__cvta_generic_to_shared(p);
}

// ---------------- 128x256 GEMM mainloop (8 warps, warp tile 64x64) ------------------
#define GLDW 20                     // words/row: 16 data + 4 pad
#define GAW (128 * GLDW)
#define GBW (256 * GLDW)
#define SE_LD 130

#define GEMM256_MAINLOOP(Aptr, Bptr, Kdim)                                           \
    uint32_t* As = gsm;                                                              \
    uint32_t* Bs = gsm + 2 * GAW;                                                    \
    const uint32_t aS = smem_u32(As);                                                \
    const uint32_t bS = smem_u32(Bs);                                                \
    const int arow = tid >> 3;                                                       \
    const int ac4  = (tid & 7) * 4;                                                  \
    const int wix  = ac4 >> 1;                                                       \
    const int lrow16 = lane & 15;                                                    \
    const int lcolA  = (lane >> 4) * 4;                                              \
    const int browB  = (lane >> 4) * 8 + (lane & 7);                                 \
    const int bcolB  = ((lane >> 3) & 1) * 4;                                        \
    const float* Ag = (Aptr) + (size_t)(bm + arow) * (Kdim) + ac4;                   \
    const float* Bg = (Bptr) + (size_t)arow * (Kdim) + ac4;                          \
    float4 ra[4], rb[8];                                                             \
    _Pragma("unroll")                                                                \
    for (int p = 0; p < 4; p++) ra[p] = *(const float4*)(Ag + (size_t)p * 32 * (Kdim)); \
    _Pragma("unroll")                                                                \
    for (int p = 0; p < 8; p++) rb[p] = *(const float4*)(Bg + (size_t)p * 32 * (Kdim)); \
    auto sts_tile = [&](int sbuf) {                                                  \
        uint32_t* ad = As + sbuf * GAW;                                              \
        uint32_t* bd = Bs + sbuf * GBW;                                              \
        _Pragma("unroll")                                                            \
        for (int p = 0; p < 4; p++) {                                                \
            uint2 a2 = make_uint2(packh2(ra[p].x, ra[p].y), packh2(ra[p].z, ra[p].w)); \
            *(uint2*)&ad[(arow + 32 * p) * GLDW + wix] = a2;                         \
        }                                                                            \
        _Pragma("unroll")                                                            \
        for (int p = 0; p < 8; p++) {                                                \
            uint2 b2 = make_uint2(packh2(rb[p].x, rb[p].y), packh2(rb[p].z, rb[p].w)); \
            *(uint2*)&bd[(arow + 32 * p) * GLDW + wix] = b2;                         \
        }                                                                            \
    };                                                                               \
    const int nchunk = (Kdim) / 32;                                                  \
    sts_tile(0);                                                                     \
    __syncthreads();                                                                 \
    for (int it = 0; it < nchunk; it++) {                                            \
        const int buf = it & 1;                                                      \
        const bool more = (it + 1 < nchunk);                                         \
        if (more) {                                                                  \
            const int kk = (it + 1) * 32;                                            \
            _Pragma("unroll")                                                        \
            for (int p = 0; p < 4; p++) ra[p] = *(const float4*)(Ag + (size_t)p * 32 * (Kdim) + kk); \
            _Pragma("unroll")                                                        \
            for (int p = 0; p < 8; p++) rb[p] = *(const float4*)(Bg + (size_t)p * 32 * (Kdim) + kk); \
        }                                                                            \
        const uint32_t abase = aS + 4 * (buf * GAW);                                 \
        const uint32_t bbase = bS + 4 * (buf * GBW);                                 \
        _Pragma("unroll")                                                            \
        for (int s16 = 0; s16 < 2; s16++) {                                          \
            const int kc = s16 * 8;                                                  \
            uint32_t af[4][4], bfr[8][2];                                            \
            _Pragma("unroll")                                                        \
            for (int mi = 0; mi < 4; mi++)                                           \
                ldsm_x4(af[mi], abase + 4 * ((wm * 64 + mi * 16 + lrow16) * GLDW + kc + lcolA)); \
            _Pragma("unroll")                                                        \
            for (int nb2 = 0; nb2 < 4; nb2++) {                                      \
                uint32_t r4[4];                                                      \
                ldsm_x4(r4, bbase + 4 * ((wn * 64 + nb2 * 16 + browB) * GLDW + kc + bcolB)); \
                bfr[2 * nb2][0] = r4[0]; bfr[2 * nb2][1] = r4[1];                    \
                bfr[2 * nb2 + 1][0] = r4[2]; bfr[2 * nb2 + 1][1] = r4[3];            \
            }                                                                        \
            _Pragma("unroll")                                                        \
            for (int mi = 0; mi < 4; mi++)                                           \
                _Pragma("unroll")                                                    \
                for (int ni = 0; ni < 8; ni++)                                       \
                    mma_f16(acc[mi][ni], af[mi], bfr[ni]);                           \
        }                                                                            \
        if (more) {                                                                  \
            sts_tile(buf ^ 1);                                                       \
            __syncthreads();                                                         \
        }                                                                            \
    }

// ---------------- fused QKV GEMM (one launch, 256-wide tiles) -----------------------
// grid (12, 32): bh 0..7 -> q cols [bh*256); 8..9 -> k; 10..11 -> v.
__global__ __launch_bounds__(256, 1) void gemm_qkv(const float* __restrict__ X,
                                                   const float* __restrict__ WQ,
                                                   const float* __restrict__ WK,
                                                   const float* __restrict__ WV,
                                                   __half* __restrict__ qout,
                                                   __half* __restrict__ kout,
                                                   __half* __restrict__ vtout,
                                                   const float* __restrict__ cosb,
                                                   const float* __restrict__ sinb) {
    extern __shared__ uint32_t gsm[];
    const int tid  = threadIdx.x;
    const int bh   = blockIdx.x;
    const int bm   = blockIdx.y * 128;
    const int warp = tid >> 5;
    const int lane = tid & 31;
    const int wm   = warp >> 2;          // 0..1
    const int wn   = warp & 3;           // 0..3 (64-col bands within 256)
    const int g    = lane >> 2;
    const int t    = lane & 3;

    const float* Bw;
    if (bh < 8)       Bw = WQ + (size_t)bh * 256 * C_SZ;
    else if (bh < 10) Bw = WK + (size_t)(bh - 8) * 256 * C_SZ;
    else              Bw = WV + (size_t)(bh - 10) * 256 * C_SZ;

    float acc[4][8][4];
#pragma unroll
    for (int mi = 0; mi < 4; mi++)
#pragma unroll
        for (int ni = 0; ni < 8; ni++)
#pragma unroll
            for (int r = 0; r < 4; r++) acc[mi][ni][r] = 0.f;

    GEMM256_MAINLOOP(X, Bw, C_SZ)

    if (bh >= 10) {
        // V: transposed half store into g_vt[B][NKV][HD][T]; tile covers 2 kv heads
        const int cbase = (bh - 10) * 256;
#pragma unroll
        for (int mi = 0; mi < 4; mi++) {
            const int gr0 = bm + wm * 64 + mi * 16 + g;
            const int gr1 = gr0 + 8;
            const int b0v = gr0 >> 11, t0v = gr0 & (T_SZ - 1);
            const int b1v = gr1 >> 11, t1v = gr1 & (T_SZ - 1);
#pragma unroll
            for (int ni = 0; ni < 8; ni++) {
                const int c = cbase + wn * 64 + ni * 8 + 2 * t;
                const int kvh = c >> 7;
                const int d = c & 127;
                size_t base0 = (((size_t)b0v * NKV + kvh) * HD + d) * T_SZ + t0v;
                size_t base1 = (((size_t)b1v * NKV + kvh) * HD + d) * T_SZ + t1v;
                vtout[base0]        = __float2half_rn(acc[mi][ni][0]);
                vtout[base0 + T_SZ] = __float2half_rn(acc[mi][ni][1]);
                vtout[base1]        = __float2half_rn(acc[mi][ni][2]);
                vtout[base1 + T_SZ] = __float2half_rn(acc[mi][ni][3]);
            }
        }
    } else {
        // Q/K: fused RoPE + RMSNorm -> half, one 128-col head at a time
        __half* Ch;
        int Nout, cb256;
        if (bh < 8) { Ch = qout; Nout = NH * HD;  cb256 = bh * 256; }
        else        { Ch = kout; Nout = NKV * HD; cb256 = (bh - 8) * 256; }

        float* sE = (float*)gsm;            // [128][130] fp32
#pragma unroll
        for (int h2 = 0; h2 < 2; h2++) {
            __syncthreads();                // drain frag reads (h2=0) / prior rope (h2=1)
            if ((wn >> 1) == h2) {
                const int wn2 = wn & 1;
#pragma unroll
                for (int mi = 0; mi < 4; mi++) {
                    const int r = wm * 64 + mi * 16 + g;
#pragma unroll
                    for (int ni = 0; ni < 8; ni++) {
                        const int c = wn2 * 64 + ni * 8 + 2 * t;
                        *(float2*)&sE[r * SE_LD + c] = make_float2(acc[mi][ni][0], acc[mi][ni][1]);
                        *(float2*)&sE[(r + 8) * SE_LD + c] = make_float2(acc[mi][ni][2], acc[mi][ni][3]);
                    }
                }
            }
            __syncthreads();

            const int row = tid >> 1;
            const int hf  = tid & 1;
            const int d0  = hf * 64;
            const int gr  = bm + row;
            const int tt  = gr & (T_SZ - 1);
            const float sgn = hf ? 1.f : -1.f;

            float rv[64];
            float ss = 0.f;
            const float* erow = sE + row * SE_LD;
            const float* cr = cosb + (size_t)tt * HD + d0;
            const float* sr = sinb + (size_t)tt * HD + d0;
#pragma unroll
            for (int i = 0; i < 64; i += 2) {
                float2 v = *(const float2*)&erow[d0 + i];
                float2 p = *(const float2*)&erow[(d0 ^ 64) + i];
                float2 c2 = *(const float2*)&cr[i];
                float2 s2 = *(const float2*)&sr[i];
                float r0 = v.x * c2.x + sgn * p.x * s2.x;
                float r1 = v.y * c2.y + sgn * p.y * s2.y;
                rv[i] = r0; rv[i + 1] = r1;
                ss += r0 * r0 + r1 * r1;
            }
            ss += __shfl_xor_sync(0xffffffffu, ss, 1);
            const float inv = rsqrtf(ss * (1.0f / HD) + RMS_EPS);

            __half2* dst = (__half2*)(Ch + (size_t)gr * Nout + cb256 + h2 * 128 + d0);
#pragma unroll
            for (int i = 0; i < 64; i += 2) {
                dst[i >> 1] = __floats2half2_rn(rv[i] * inv, rv[i + 1] * inv);
            }
        }
    }
}

// ---------------- output projection GEMM (256-wide tiles, fp32 out) -----------------
__global__ __launch_bounds__(256, 1) void gemm_proj(const float* __restrict__ A,
                                                    const float* __restrict__ B,
                                                    float* __restrict__ C) {
    extern __shared__ uint32_t gsm[];
    const int tid  = threadIdx.x;
    const int bn   = blockIdx.x * 256;
    const int bm   = blockIdx.y * 128;
    const int warp = tid >> 5;
    const int lane = tid & 31;
    const int wm   = warp >> 2;
    const int wn   = warp & 3;
    const int g    = lane >> 2;
    const int t    = lane & 3;

    const float* Bw = B + (size_t)bn * C_SZ;

    float acc[4][8][4];
#pragma unroll
    for (int mi = 0; mi < 4; mi++)
#pragma unroll
        for (int ni = 0; ni < 8; ni++)
#pragma unroll
            for (int r = 0; r < 4; r++) acc[mi][ni][r] = 0.f;

    GEMM256_MAINLOOP(A, Bw, C_SZ)

#pragma unroll
    for (int mi = 0; mi < 4; mi++) {
        const int r = bm + wm * 64 + mi * 16 + g;
#pragma unroll
        for (int ni = 0; ni < 8; ni++) {
            const int c = bn + wn * 64 + ni * 8 + 2 * t;
            *(float2*)&C[(size_t)r * C_SZ + c] = make_float2(acc[mi][ni][0], acc[mi][ni][1]);
            *(float2*)&C[(size_t)(r + 8) * C_SZ + c] = make_float2(acc[mi][ni][2], acc[mi][ni][3]);
        }
    }
}

// ---------------- flash attention: BM=64, static-shift softmax, branch-free fast path
#define BM 64
#define BN 64
#define AK_LD 68
#define AV_LD 36
#define AK_TILE (BN * AK_LD)
#define AV_TILE (HD * AV_LD)
#define NSTG 2

__global__ __launch_bounds__(128, 2) void attn_f16(const __half* __restrict__ qb,
                                                   const __half* __restrict__ kb,
                                                   const __half* __restrict__ vtb,
                                                   float* __restrict__ yb) {
    extern __shared__ uint32_t smu[];
    uint32_t* sK  = smu;                       // [2][64][68]
    uint32_t* sVt = smu + NSTG * AK_TILE;      // [2][128][36]
    const uint32_t kS = smem_u32(sK);
    const uint32_t vS = smem_u32(sVt);

    const int qt = gridDim.x - 1 - blockIdx.x;   // heavy tiles first
    const int h  = blockIdx.y;
    const int b  = blockIdx.z;
    const int kvh = h >> 2;
    const int qs = qt * BM;
    const int tid  = threadIdx.x;
    const int w    = tid >> 5;
    const int lane = tid & 31;
    const int g    = lane >> 2;
    const int t    = lane & 3;
    const int w16  = w * 16;
    const int lrow8 = lane & 7;
    const int lcolB = ((lane >> 3) & 1) * 4;

    uint32_t qa[8][4];
    {
        const uint32_t* q0 = (const uint32_t*)(qb + (size_t)(b * T_SZ + qs + w16 + g) * (NH * HD) + h * HD);
        const uint32_t* q1 = q0 + 8 * (NH * HD / 2);
#pragma unroll
        for (int s16 = 0; s16 < 8; s16++) {
            qa[s16][0] = q0[s16 * 8 + t];
            qa[s16][1] = q1[s16 * 8 + t];
            qa[s16][2] = q0[s16 * 8 + t + 4];
            qa[s16][3] = q1[s16 * 8 + t + 4];
        }
    }

    float l0 = 0.f, l1 = 0.f;
    float o[16][4];
#pragma unroll
    for (int dt = 0; dt < 16; dt++)
#pragma unroll
        for (int r = 0; r < 4; r++) o[dt][r] = 0.f;

    const int row0 = qs + w16 + g;
    const int row1 = row0 + 8;

    const int kr = tid >> 1, kh2 = tid & 1;
    const __half* kbase = kb + (size_t)b * T_SZ * (NKV * HD) + kvh * HD;
    const __half* vbase = vtb + (((size_t)b * NKV + kvh) * HD + tid) * T_SZ;

    auto stage_kv = [&](int sbuf, int ks) {
        uint32_t kd = smem_u32(sK + sbuf * AK_TILE + kr * AK_LD + kh2 * 32);
        const __half* ksrc = kbase + (size_t)(ks + kr) * (NKV * HD) + kh2 * 64;
#pragma unroll
        for (int i = 0; i < 8; i++) CP_ASYNC16(kd + 16 * i, ksrc + 8 * i);
        uint32_t vd = smem_u32(sVt + sbuf * AV_TILE + tid * AV_LD);
        const __half* vsrc = vbase + ks;
#pragma unroll
        for (int i = 0; i < 8; i++) CP_ASYNC16(vd + 16 * i, vsrc + 8 * i);
    };

    const int ntile = qt + 1;
    stage_kv(0, 0);
    CP_COMMIT();

    for (int it = 0; it < ntile; it++) {
        const int buf = it & 1;
        const int ks = it * BN;
        CP_WAIT(0);
        __syncthreads();
        if (it + 1 < ntile) {
            stage_kv(buf ^ 1, (it + 1) * BN);
            CP_COMMIT();
        }

        const int lim = qs + w16 + 15 - ks;     // max valid local col for this warp
        if (lim < 0) continue;                   // fully masked for this warp
        const bool full = (lim >= 63);           // branch-free fast path selector

        const uint32_t kbuf = kS + 4 * (buf * AK_TILE);
        const uint32_t vbuf = vS + 4 * (buf * AV_TILE);

        // ---- S = Q K^T ----
        float s[8][4];
#pragma unroll
        for (int nb = 0; nb < 8; nb++)
#pragma unroll
            for (int r = 0; r < 4; r++) s[nb][r] = 0.f;

        if (full) {
            // fast path: no inner-bound checks (vast majority of tiles)
#pragma unroll
            for (int s16 = 0; s16 < 8; s16++) {
#pragma unroll
                for (int nb = 0; nb < 8; nb++) {
                    uint32_t bf[2];
                    ldsm_x2(bf, kbuf + 4 * ((nb * 8 + lrow8) * AK_LD + s16 * 8 + lcolB));
                    mma_f16(s[nb], qa[s16], bf);
                }
            }
        } else {
            const int ntmax = (lim >> 3) + 1;
            for (int nb = 0; nb < ntmax; nb++) {
#pragma unroll
                for (int s16 = 0; s16 < 8; s16++) {
                    uint32_t bf[2];
                    ldsm_x2(bf, kbuf + 4 * ((nb * 8 + lrow8) * AK_LD + s16 * 8 + lcolB));
                    mma_f16(s[nb], qa[s16], bf);
                }
            }
        }

        // ---- static-shift softmax: p = exp(s*scale - 3); no max, no rescale ----
        const bool needs_mask = (ks + BN - 1) > (qs + w16);
        float rs0 = 0.f, rs1 = 0.f;
#pragma unroll
        for (int nb = 0; nb < 8; nb++) {
#pragma unroll
            for (int ci = 0; ci < 2; ci++) {
                const int col = ks + nb * 8 + 2 * t + ci;
                float p0 = __expf(fmaf(s[nb][ci], ATT_SCALE, -SM_SHIFT));
                float p1 = __expf(fmaf(s[nb][2 + ci], ATT_SCALE, -SM_SHIFT));
                if (needs_mask) {
                    if (col > row0) p0 = 0.f;
                    if (col > row1) p1 = 0.f;
                }
                s[nb][ci] = p0;
                s[nb][2 + ci] = p1;
                rs0 += p0;
                rs1 += p1;
            }
        }
        rs0 += __shfl_xor_sync(0xffffffffu, rs0, 1);
        rs0 += __shfl_xor_sync(0xffffffffu, rs0, 2);
        rs1 += __shfl_xor_sync(0xffffffffu, rs1, 1);
        rs1 += __shfl_xor_sync(0xffffffffu, rs1, 2);
        l0 += rs0;
        l1 += rs1;

        // ---- O += P V : accumulator -> half2 A-frags directly ----
        if (full) {
#pragma unroll
            for (int j = 0; j < 4; j++) {
                uint32_t pa[4];
                pa[0] = packh2(s[2 * j][0], s[2 * j][1]);
                pa[1] = packh2(s[2 * j][2], s[2 * j][3]);
                pa[2] = packh2(s[2 * j + 1][0], s[2 * j + 1][1]);
                pa[3] = packh2(s[2 * j + 1][2], s[2 * j + 1][3]);
#pragma unroll
                for (int dt = 0; dt < 16; dt++) {
                    uint32_t bf[2];
                    ldsm_x2(bf, vbuf + 4 * ((dt * 8 + lrow8) * AV_LD + j * 8 + lcolB));
                    mma_f16(o[dt], pa, bf);
                }
            }
        } else {
            const int jmax = (lim >> 4) + 1;
            for (int j = 0; j < jmax; j++) {
                uint32_t pa[4];
                pa[0] = packh2(s[2 * j][0], s[2 * j][1]);
                pa[1] = packh2(s[2 * j][2], s[2 * j][3]);
                pa[2] = packh2(s[2 * j + 1][0], s[2 * j + 1][1]);
                pa[3] = packh2(s[2 * j + 1][2], s[2 * j + 1][3]);
#pragma unroll
                for (int dt = 0; dt < 16; dt++) {
                    uint32_t bf[2];
                    ldsm_x2(bf, vbuf + 4 * ((dt * 8 + lrow8) * AV_LD + j * 8 + lcolB));
                    mma_f16(o[dt], pa, bf);
                }
            }
        }
    }

    const float inv0 = 1.0f / l0;
    const float inv1 = 1.0f / l1;
    float* dst0 = yb + (size_t)(b * T_SZ + row0) * C_SZ + h * HD;
    float* dst1 = yb + (size_t)(b * T_SZ + row1) * C_SZ + h * HD;
#pragma unroll
    for (int dt = 0; dt < 16; dt++) {
        *(float2*)&dst0[dt * 8 + 2 * t] = make_float2(o[dt][0] * inv0, o[dt][1] * inv0);
        *(float2*)&dst1[dt * 8 + 2 * t] = make_float2(o[dt][2] * inv1, o[dt][3] * inv1);
    }
}

// ---------------- launch ---------------------------------------------------------
extern "C" void kernel_launch(void* const* d_in, const int* in_sizes, int n_in,
                              void* d_out, int out_size) {
    const float* x     = (const float*)d_in[0];
    const float* cosb  = (const float*)d_in[1];
    const float* sinb  = (const float*)d_in[2];
    const float* wq    = (const float*)d_in[3];
    const float* wk    = (const float*)d_in[4];
    const float* wv    = (const float*)d_in[5];
    const float* wproj = (const float*)d_in[6];
    float* out = (float*)d_out;

    __half *qp, *kp, *vtp;
    float *yp;
    cudaGetSymbolAddress((void**)&qp,  g_q);
    cudaGetSymbolAddress((void**)&kp,  g_k);
    cudaGetSymbolAddress((void**)&vtp, g_vt);
    cudaGetSymbolAddress((void**)&yp,  g_y);

    const int M = B_SZ * T_SZ;   // 4096

    const int stage_smem = 2 * (GAW + GBW) * sizeof(uint32_t);     // 61440
    const int rope_smem  = 128 * SE_LD * sizeof(float);            // 66560
    const int qkv_smem   = rope_smem > stage_smem ? rope_smem : stage_smem;
    cudaFuncSetAttribute(gemm_qkv,  cudaFuncAttributeMaxDynamicSharedMemorySize, qkv_smem);
    cudaFuncSetAttribute(gemm_proj, cudaFuncAttributeMaxDynamicSharedMemorySize, stage_smem);

    // fused QKV: 12 col-blocks (8 q + 2 k + 2 v) x 32 row-tiles
    gemm_qkv<<<dim3(12, M / 128), 256, qkv_smem>>>(
        x, wq, wk, wv, qp, kp, vtp, cosb, sinb);

    // attention: BM=64, 4 warps, 2 CTAs/SM, static-shift softmax, branch-free fast path
    const int attn_smem = NSTG * (AK_TILE + AV_TILE) * sizeof(uint32_t);  // 71680
    cudaFuncSetAttribute(attn_f16, cudaFuncAttributeMaxDynamicSharedMemorySize, attn_smem);
    attn_f16<<<dim3(T_SZ / BM, NH, B_SZ), 128, attn_smem>>>(qp, kp, vtp, yp);

    // output projection: 8 col-tiles x 32 row-tiles
    gemm_proj<<<dim3(C_SZ / 256, M / 128), 256, stage_smem>>>(yp, wproj, out);
}

// round 17
// speedup vs baseline: 1.1193x; 1.1193x over previous
#include <cuda_runtime.h>
#include <cuda_fp16.h>
#include <cstdint>

#define B_SZ 2
#define T_SZ 2048
#define C_SZ 2048
#define NH 16
#define NKV 4
#define HD 128
#define RMS_EPS 1.1920929e-07f
#define ATT_SCALE 0.08838834764831845f   // 1/sqrt(128)
#define SM_SHIFT 3.0f                    // static softmax shift (|s|<=11.32)

// ---------------- scratch (static device globals; no allocation) ----------------
__device__ __half g_q[(size_t)B_SZ * T_SZ * NH * HD];           // q (rope+rms) half
__device__ __half g_k[(size_t)B_SZ * T_SZ * NKV * HD];          // k (rope+rms) half
__device__ __half g_vt[(size_t)B_SZ * NKV * HD * T_SZ];         // v transposed half
__device__ float  g_y[(size_t)B_SZ * T_SZ * C_SZ];              // attn out fp32

// ---------------- helpers ----------------------------------------------------------
__device__ __forceinline__ uint32_t packh2(float lo, float hi) {
    __half2 h = __floats2half2_rn(lo, hi);
    return *(uint32_t*)&h;
}

__device__ __forceinline__ void mma_f16(float* c, const uint32_t* a, const uint32_t* b) {
    asm volatile("mma.sync.aligned.m16n8k16.row.col.f32.f16.f16.f32 "
                 "{%0,%1,%2,%3}, {%4,%5,%6,%7}, {%8,%9}, {%0,%1,%2,%3};"
                 : "+f"(c[0]), "+f"(c[1]), "+f"(c[2]), "+f"(c[3])
                 : "r"(a[0]), "r"(a[1]), "r"(a[2]), "r"(a[3]),
                   "r"(b[0]), "r"(b[1]));
}

__device__ __forceinline__ void ldsm_x4(uint32_t* r, uint32_t saddr) {
    asm volatile("ldmatrix.sync.aligned.m8n8.x4.shared.b16 {%0,%1,%2,%3}, [%4];"
                 : "=r"(r[0]), "=r"(r[1]), "=r"(r[2]), "=r"(r[3]) : "r"(saddr));
}

#define CP_ASYNC16(dst_u32, src_ptr) \
    asm volatile("cp.async.cg.shared.global [%0], [%1], 16;" :: "r"(dst_u32), "l"(src_ptr))
#define CP_COMMIT() asm volatile("cp.async.commit_group;" ::: "memory")
#define CP_WAIT(n)  asm volatile("cp.async.wait_group %0;" :: "n"(n) : "memory")

__device__ __forceinline__ uint32_t smem_u32(const void* p) {
    return (uint32_t)__cvta_generic_to_shared(p);
}

// ---------------- 128x256 GEMM mainloop (8 warps, warp tile 64x64) ------------------
#define GLDW 20                     // words/row: 16 data + 4 pad
#define GAW (128 * GLDW)
#define GBW (256 * GLDW)
#define SE_LD 130

#define GEMM256_MAINLOOP(Aptr, Bptr, Kdim)                                           \
    uint32_t* As = gsm;                                                              \
    uint32_t* Bs = gsm + 2 * GAW;                                                    \
    const uint32_t aS = smem_u32(As);                                                \
    const uint32_t bS = smem_u32(Bs);                                                \
    const int arow = tid >> 3;                                                       \
    const int ac4  = (tid & 7) * 4;                                                  \
    const int wix  = ac4 >> 1;                                                       \
    const int lrow16 = lane & 15;                                                    \
    const int lcolA  = (lane >> 4) * 4;                                              \
    const int browB  = (lane >> 4) * 8 + (lane & 7);                                 \
    const int bcolB  = ((lane >> 3) & 1) * 4;                                        \
    const float* Ag = (Aptr) + (size_t)(bm + arow) * (Kdim) + ac4;                   \
    const float* Bg = (Bptr) + (size_t)arow * (Kdim) + ac4;                          \
    float4 ra[4], rb[8];                                                             \
    _Pragma("unroll")                                                                \
    for (int p = 0; p < 4; p++) ra[p] = *(const float4*)(Ag + (size_t)p * 32 * (Kdim)); \
    _Pragma("unroll")                                                                \
    for (int p = 0; p < 8; p++) rb[p] = *(const float4*)(Bg + (size_t)p * 32 * (Kdim)); \
    auto sts_tile = [&](int sbuf) {                                                  \
        uint32_t* ad = As + sbuf * GAW;                                              \
        uint32_t* bd = Bs + sbuf * GBW;                                              \
        _Pragma("unroll")                                                            \
        for (int p = 0; p < 4; p++) {                                                \
            uint2 a2 = make_uint2(packh2(ra[p].x, ra[p].y), packh2(ra[p].z, ra[p].w)); \
            *(uint2*)&ad[(arow + 32 * p) * GLDW + wix] = a2;                         \
        }                                                                            \
        _Pragma("unroll")                                                            \
        for (int p = 0; p < 8; p++) {                                                \
            uint2 b2 = make_uint2(packh2(rb[p].x, rb[p].y), packh2(rb[p].z, rb[p].w)); \
            *(uint2*)&bd[(arow + 32 * p) * GLDW + wix] = b2;                         \
        }                                                                            \
    };                                                                               \
    const int nchunk = (Kdim) / 32;                                                  \
    sts_tile(0);                                                                     \
    __syncthreads();                                                                 \
    for (int it = 0; it < nchunk; it++) {                                            \
        const int buf = it & 1;                                                      \
        const bool more = (it + 1 < nchunk);                                         \
        if (more) {                                                                  \
            const int kk = (it + 1) * 32;                                            \
            _Pragma("unroll")                                                        \
            for (int p = 0; p < 4; p++) ra[p] = *(const float4*)(Ag + (size_t)p * 32 * (Kdim) + kk); \
            _Pragma("unroll")                                                        \
            for (int p = 0; p < 8; p++) rb[p] = *(const float4*)(Bg + (size_t)p * 32 * (Kdim) + kk); \
        }                                                                            \
        const uint32_t abase = aS + 4 * (buf * GAW);                                 \
        const uint32_t bbase = bS + 4 * (buf * GBW);                                 \
        _Pragma("unroll")                                                            \
        for (int s16 = 0; s16 < 2; s16++) {                                          \
            const int kc = s16 * 8;                                                  \
            uint32_t af[4][4], bfr[8][2];                                            \
            _Pragma("unroll")                                                        \
            for (int mi = 0; mi < 4; mi++)                                           \
                ldsm_x4(af[mi], abase + 4 * ((wm * 64 + mi * 16 + lrow16) * GLDW + kc + lcolA)); \
            _Pragma("unroll")                                                        \
            for (int nb2 = 0; nb2 < 4; nb2++) {                                      \
                uint32_t r4[4];                                                      \
                ldsm_x4(r4, bbase + 4 * ((wn * 64 + nb2 * 16 + browB) * GLDW + kc + bcolB)); \
                bfr[2 * nb2][0] = r4[0]; bfr[2 * nb2][1] = r4[1];                    \
                bfr[2 * nb2 + 1][0] = r4[2]; bfr[2 * nb2 + 1][1] = r4[3];            \
            }                                                                        \
            _Pragma("unroll")                                                        \
            for (int mi = 0; mi < 4; mi++)                                           \
                _Pragma("unroll")                                                    \
                for (int ni = 0; ni < 8; ni++)                                       \
                    mma_f16(acc[mi][ni], af[mi], bfr[ni]);                           \
        }                                                                            \
        if (more) {                                                                  \
            sts_tile(buf ^ 1);                                                       \
            __syncthreads();                                                         \
        }                                                                            \
    }

// ---------------- fused QKV GEMM (one launch, 256-wide tiles) -----------------------
// grid (12, 32): bh 0..7 -> q cols [bh*256); 8..9 -> k; 10..11 -> v.
__global__ __launch_bounds__(256, 1) void gemm_qkv(const float* __restrict__ X,
                                                   const float* __restrict__ WQ,
                                                   const float* __restrict__ WK,
                                                   const float* __restrict__ WV,
                                                   __half* __restrict__ qout,
                                                   __half* __restrict__ kout,
                                                   __half* __restrict__ vtout,
                                                   const float* __restrict__ cosb,
                                                   const float* __restrict__ sinb) {
    extern __shared__ uint32_t gsm[];
    const int tid  = threadIdx.x;
    const int bh   = blockIdx.x;
    const int bm   = blockIdx.y * 128;
    const int warp = tid >> 5;
    const int lane = tid & 31;
    const int wm   = warp >> 2;          // 0..1
    const int wn   = warp & 3;           // 0..3 (64-col bands within 256)
    const int g    = lane >> 2;
    const int t    = lane & 3;

    const float* Bw;
    if (bh < 8)       Bw = WQ + (size_t)bh * 256 * C_SZ;
    else if (bh < 10) Bw = WK + (size_t)(bh - 8) * 256 * C_SZ;
    else              Bw = WV + (size_t)(bh - 10) * 256 * C_SZ;

    float acc[4][8][4];
#pragma unroll
    for (int mi = 0; mi < 4; mi++)
#pragma unroll
        for (int ni = 0; ni < 8; ni++)
#pragma unroll
            for (int r = 0; r < 4; r++) acc[mi][ni][r] = 0.f;

    GEMM256_MAINLOOP(X, Bw, C_SZ)

    if (bh >= 10) {
        // V: transposed half store into g_vt[B][NKV][HD][T]; tile covers 2 kv heads
        const int cbase = (bh - 10) * 256;
#pragma unroll
        for (int mi = 0; mi < 4; mi++) {
            const int gr0 = bm + wm * 64 + mi * 16 + g;
            const int gr1 = gr0 + 8;
            const int b0v = gr0 >> 11, t0v = gr0 & (T_SZ - 1);
            const int b1v = gr1 >> 11, t1v = gr1 & (T_SZ - 1);
#pragma unroll
            for (int ni = 0; ni < 8; ni++) {
                const int c = cbase + wn * 64 + ni * 8 + 2 * t;
                const int kvh = c >> 7;
                const int d = c & 127;
                size_t base0 = (((size_t)b0v * NKV + kvh) * HD + d) * T_SZ + t0v;
                size_t base1 = (((size_t)b1v * NKV + kvh) * HD + d) * T_SZ + t1v;
                vtout[base0]        = __float2half_rn(acc[mi][ni][0]);
                vtout[base0 + T_SZ] = __float2half_rn(acc[mi][ni][1]);
                vtout[base1]        = __float2half_rn(acc[mi][ni][2]);
                vtout[base1 + T_SZ] = __float2half_rn(acc[mi][ni][3]);
            }
        }
    } else {
        // Q/K: fused RoPE + RMSNorm -> half, one 128-col head at a time
        __half* Ch;
        int Nout, cb256;
        if (bh < 8) { Ch = qout; Nout = NH * HD;  cb256 = bh * 256; }
        else        { Ch = kout; Nout = NKV * HD; cb256 = (bh - 8) * 256; }

        float* sE = (float*)gsm;            // [128][130] fp32
#pragma unroll
        for (int h2 = 0; h2 < 2; h2++) {
            __syncthreads();                // drain frag reads (h2=0) / prior rope (h2=1)
            if ((wn >> 1) == h2) {
                const int wn2 = wn & 1;
#pragma unroll
                for (int mi = 0; mi < 4; mi++) {
                    const int r = wm * 64 + mi * 16 + g;
#pragma unroll
                    for (int ni = 0; ni < 8; ni++) {
                        const int c = wn2 * 64 + ni * 8 + 2 * t;
                        *(float2*)&sE[r * SE_LD + c] = make_float2(acc[mi][ni][0], acc[mi][ni][1]);
                        *(float2*)&sE[(r + 8) * SE_LD + c] = make_float2(acc[mi][ni][2], acc[mi][ni][3]);
                    }
                }
            }
            __syncthreads();

            const int row = tid >> 1;
            const int hf  = tid & 1;
            const int d0  = hf * 64;
            const int gr  = bm + row;
            const int tt  = gr & (T_SZ - 1);
            const float sgn = hf ? 1.f : -1.f;

            float rv[64];
            float ss = 0.f;
            const float* erow = sE + row * SE_LD;
            const float* cr = cosb + (size_t)tt * HD + d0;
            const float* sr = sinb + (size_t)tt * HD + d0;
#pragma unroll
            for (int i = 0; i < 64; i += 2) {
                float2 v = *(const float2*)&erow[d0 + i];
                float2 p = *(const float2*)&erow[(d0 ^ 64) + i];
                float2 c2 = *(const float2*)&cr[i];
                float2 s2 = *(const float2*)&sr[i];
                float r0 = v.x * c2.x + sgn * p.x * s2.x;
                float r1 = v.y * c2.y + sgn * p.y * s2.y;
                rv[i] = r0; rv[i + 1] = r1;
                ss += r0 * r0 + r1 * r1;
            }
            ss += __shfl_xor_sync(0xffffffffu, ss, 1);
            const float inv = rsqrtf(ss * (1.0f / HD) + RMS_EPS);

            __half2* dst = (__half2*)(Ch + (size_t)gr * Nout + cb256 + h2 * 128 + d0);
#pragma unroll
            for (int i = 0; i < 64; i += 2) {
                dst[i >> 1] = __floats2half2_rn(rv[i] * inv, rv[i + 1] * inv);
            }
        }
    }
}

// ---------------- output projection GEMM (256-wide tiles, fp32 out) -----------------
__global__ __launch_bounds__(256, 1) void gemm_proj(const float* __restrict__ A,
                                                    const float* __restrict__ B,
                                                    float* __restrict__ C) {
    extern __shared__ uint32_t gsm[];
    const int tid  = threadIdx.x;
    const int bn   = blockIdx.x * 256;
    const int bm   = blockIdx.y * 128;
    const int warp = tid >> 5;
    const int lane = tid & 31;
    const int wm   = warp >> 2;
    const int wn   = warp & 3;
    const int g    = lane >> 2;
    const int t    = lane & 3;

    const float* Bw = B + (size_t)bn * C_SZ;

    float acc[4][8][4];
#pragma unroll
    for (int mi = 0; mi < 4; mi++)
#pragma unroll
        for (int ni = 0; ni < 8; ni++)
#pragma unroll
            for (int r = 0; r < 4; r++) acc[mi][ni][r] = 0.f;

    GEMM256_MAINLOOP(A, Bw, C_SZ)

#pragma unroll
    for (int mi = 0; mi < 4; mi++) {
        const int r = bm + wm * 64 + mi * 16 + g;
#pragma unroll
        for (int ni = 0; ni < 8; ni++) {
            const int c = bn + wn * 64 + ni * 8 + 2 * t;
            *(float2*)&C[(size_t)r * C_SZ + c] = make_float2(acc[mi][ni][0], acc[mi][ni][1]);
            *(float2*)&C[(size_t)(r + 8) * C_SZ + c] = make_float2(acc[mi][ni][2], acc[mi][ni][3]);
        }
    }
}

// ---------------- flash attention: BM=64, static-shift softmax, single path ---------
// Unconditional unrolled mma loops: masked columns are zeroed by the softmax mask
// (for nb >= ntmax: col > row1 >= row0 for every fragment position), so the extra
// diagonal-tile work (~2%) buys a branch-free single instruction stream.
#define BM 64
#define BN 64
#define AK_LD 68
#define AV_LD 36
#define AK_TILE (BN * AK_LD)
#define AV_TILE (HD * AV_LD)
#define NSTG 2

__global__ __launch_bounds__(128, 2) void attn_f16(const __half* __restrict__ qb,
                                                   const __half* __restrict__ kb,
                                                   const __half* __restrict__ vtb,
                                                   float* __restrict__ yb) {
    extern __shared__ uint32_t smu[];
    uint32_t* sK  = smu;                       // [2][64][68]
    uint32_t* sVt = smu + NSTG * AK_TILE;      // [2][128][36]
    const uint32_t kS = smem_u32(sK);
    const uint32_t vS = smem_u32(sVt);

    const int qt = gridDim.x - 1 - blockIdx.x;   // heavy tiles first
    const int h  = blockIdx.y;
    const int b  = blockIdx.z;
    const int kvh = h >> 2;
    const int qs = qt * BM;
    const int tid  = threadIdx.x;
    const int w    = tid >> 5;
    const int lane = tid & 31;
    const int g    = lane >> 2;
    const int t    = lane & 3;
    const int w16  = w * 16;
    const int browB = (lane >> 4) * 8 + (lane & 7);
    const int bcolB = ((lane >> 3) & 1) * 4;

    uint32_t qa[8][4];
    {
        const uint32_t* q0 = (const uint32_t*)(qb + (size_t)(b * T_SZ + qs + w16 + g) * (NH * HD) + h * HD);
        const uint32_t* q1 = q0 + 8 * (NH * HD / 2);
#pragma unroll
        for (int s16 = 0; s16 < 8; s16++) {
            qa[s16][0] = q0[s16 * 8 + t];
            qa[s16][1] = q1[s16 * 8 + t];
            qa[s16][2] = q0[s16 * 8 + t + 4];
            qa[s16][3] = q1[s16 * 8 + t + 4];
        }
    }

    float l0 = 0.f, l1 = 0.f;
    float o[16][4];
#pragma unroll
    for (int dt = 0; dt < 16; dt++)
#pragma unroll
        for (int r = 0; r < 4; r++) o[dt][r] = 0.f;

    const int row0 = qs + w16 + g;
    const int row1 = row0 + 8;

    const int kr = tid >> 1, kh2 = tid & 1;
    const __half* kbase = kb + (size_t)b * T_SZ * (NKV * HD) + kvh * HD;
    const __half* vbase = vtb + (((size_t)b * NKV + kvh) * HD + tid) * T_SZ;

    auto stage_kv = [&](int sbuf, int ks) {
        uint32_t kd = smem_u32(sK + sbuf * AK_TILE + kr * AK_LD + kh2 * 32);
        const __half* ksrc = kbase + (size_t)(ks + kr) * (NKV * HD) + kh2 * 64;
#pragma unroll
        for (int i = 0; i < 8; i++) CP_ASYNC16(kd + 16 * i, ksrc + 8 * i);
        uint32_t vd = smem_u32(sVt + sbuf * AV_TILE + tid * AV_LD);
        const __half* vsrc = vbase + ks;
#pragma unroll
        for (int i = 0; i < 8; i++) CP_ASYNC16(vd + 16 * i, vsrc + 8 * i);
    };

    const int ntile = qt + 1;
    stage_kv(0, 0);
    CP_COMMIT();

    for (int it = 0; it < ntile; it++) {
        const int buf = it & 1;
        const int ks = it * BN;
        CP_WAIT(0);
        __syncthreads();
        if (it + 1 < ntile) {
            stage_kv(buf ^ 1, (it + 1) * BN);
            CP_COMMIT();
        }

        const int lim = qs + w16 + 15 - ks;     // max valid local col for this warp
        if (lim < 0) continue;                   // whole warp-tile masked (uniform branch)

        const uint32_t kbuf = kS + 4 * (buf * AK_TILE);
        const uint32_t vbuf = vS + 4 * (buf * AV_TILE);

        // ---- S = Q K^T (unconditional; ldsm x4 covering 2 n-blocks per load) ----
        float s[8][4];
#pragma unroll
        for (int nb = 0; nb < 8; nb++)
#pragma unroll
            for (int r = 0; r < 4; r++) s[nb][r] = 0.f;

#pragma unroll
        for (int s16 = 0; s16 < 8; s16++) {
#pragma unroll
            for (int nb2 = 0; nb2 < 4; nb2++) {
                uint32_t r4[4];
                ldsm_x4(r4, kbuf + 4 * ((nb2 * 16 + browB) * AK_LD + s16 * 8 + bcolB));
                mma_f16(s[2 * nb2], qa[s16], r4);
                mma_f16(s[2 * nb2 + 1], qa[s16], r4 + 2);
            }
        }

        // ---- static-shift softmax: p = exp(s*scale - 3); mask zeroes invalid cols ----
        const bool needs_mask = (ks + BN - 1) > (qs + w16);
        float rs0 = 0.f, rs1 = 0.f;
#pragma unroll
        for (int nb = 0; nb < 8; nb++) {
#pragma unroll
            for (int ci = 0; ci < 2; ci++) {
                const int col = ks + nb * 8 + 2 * t + ci;
                float p0 = __expf(fmaf(s[nb][ci], ATT_SCALE, -SM_SHIFT));
                float p1 = __expf(fmaf(s[nb][2 + ci], ATT_SCALE, -SM_SHIFT));
                if (needs_mask) {
                    if (col > row0) p0 = 0.f;
                    if (col > row1) p1 = 0.f;
                }
                s[nb][ci] = p0;
                s[nb][2 + ci] = p1;
                rs0 += p0;
                rs1 += p1;
            }
        }
        rs0 += __shfl_xor_sync(0xffffffffu, rs0, 1);
        rs0 += __shfl_xor_sync(0xffffffffu, rs0, 2);
        rs1 += __shfl_xor_sync(0xffffffffu, rs1, 1);
        rs1 += __shfl_xor_sync(0xffffffffu, rs1, 2);
        l0 += rs0;
        l1 += rs1;

        // ---- O += P V (unconditional; ldsm x4 covering 2 d-blocks per load) ----
#pragma unroll
        for (int j = 0; j < 4; j++) {
            uint32_t pa[4];
            pa[0] = packh2(s[2 * j][0], s[2 * j][1]);
            pa[1] = packh2(s[2 * j][2], s[2 * j][3]);
            pa[2] = packh2(s[2 * j + 1][0], s[2 * j + 1][1]);
            pa[3] = packh2(s[2 * j + 1][2], s[2 * j + 1][3]);
#pragma unroll
            for (int dt2 = 0; dt2 < 8; dt2++) {
                uint32_t r4[4];
                ldsm_x4(r4, vbuf + 4 * ((dt2 * 16 + browB) * AV_LD + j * 8 + bcolB));
                mma_f16(o[2 * dt2], pa, r4);
                mma_f16(o[2 * dt2 + 1], pa, r4 + 2);
            }
        }
    }

    const float inv0 = 1.0f / l0;
    const float inv1 = 1.0f / l1;
    float* dst0 = yb + (size_t)(b * T_SZ + row0) * C_SZ + h * HD;
    float* dst1 = yb + (size_t)(b * T_SZ + row1) * C_SZ + h * HD;
#pragma unroll
    for (int dt = 0; dt < 16; dt++) {
        *(float2*)&dst0[dt * 8 + 2 * t] = make_float2(o[dt][0] * inv0, o[dt][1] * inv0);
        *(float2*)&dst1[dt * 8 + 2 * t] = make_float2(o[dt][2] * inv1, o[dt][3] * inv1);
    }
}

// ---------------- launch ---------------------------------------------------------
extern "C" void kernel_launch(void* const* d_in, const int* in_sizes, int n_in,
                              void* d_out, int out_size) {
    const float* x     = (const float*)d_in[0];
    const float* cosb  = (const float*)d_in[1];
    const float* sinb  = (const float*)d_in[2];
    const float* wq    = (const float*)d_in[3];
    const float* wk    = (const float*)d_in[4];
    const float* wv    = (const float*)d_in[5];
    const float* wproj = (const float*)d_in[6];
    float* out = (float*)d_out;

    __half *qp, *kp, *vtp;
    float *yp;
    cudaGetSymbolAddress((void**)&qp,  g_q);
    cudaGetSymbolAddress((void**)&kp,  g_k);
    cudaGetSymbolAddress((void**)&vtp, g_vt);
    cudaGetSymbolAddress((void**)&yp,  g_y);

    const int M = B_SZ * T_SZ;   // 4096

    const int stage_smem = 2 * (GAW + GBW) * sizeof(uint32_t);     // 61440
    const int rope_smem  = 128 * SE_LD * sizeof(float);            // 66560
    const int qkv_smem   = rope_smem > stage_smem ? rope_smem : stage_smem;
    cudaFuncSetAttribute(gemm_qkv,  cudaFuncAttributeMaxDynamicSharedMemorySize, qkv_smem);
    cudaFuncSetAttribute(gemm_proj, cudaFuncAttributeMaxDynamicSharedMemorySize, stage_smem);

    // fused QKV: 12 col-blocks (8 q + 2 k + 2 v) x 32 row-tiles
    gemm_qkv<<<dim3(12, M / 128), 256, qkv_smem>>>(
        x, wq, wk, wv, qp, kp, vtp, cosb, sinb);

    // attention: BM=64, 4 warps, 2 CTAs/SM, static-shift softmax, single path
    const int attn_smem = NSTG * (AK_TILE + AV_TILE) * sizeof(uint32_t);  // 71680
    cudaFuncSetAttribute(attn_f16, cudaFuncAttributeMaxDynamicSharedMemorySize, attn_smem);
    attn_f16<<<dim3(T_SZ / BM, NH, B_SZ), 128, attn_smem>>>(qp, kp, vtp, yp);

    // output projection: 8 col-tiles x 32 row-tiles
    gemm_proj<<<dim3(C_SZ / 256, M / 128), 256, stage_smem>>>(yp, wproj, out);
}